// round 2
// baseline (speedup 1.0000x reference)
#include <cuda_runtime.h>
#include <cuda_fp16.h>

// Problem dims
#define T_STEPS 8192
#define IN_DIM  512
#define H_DIM   2048
#define G_DIM   8192   // 4*H
#define OUT_DIM 512

// Persistent recurrence kernel config
#define NCTA      148
#define NTHR      256
#define SROWS_MAX 54                      // rows of W_hh kept in SMEM per CTA (rest streamed via L1)
#define SMEM_W_BYTES   (SROWS_MAX * H_DIM * 2)          // 221184
#define SMEM_H_BYTES   (H_DIM * 4)                       // 8192
#define SMEM_BYTES     (SMEM_W_BYTES + SMEM_H_BYTES + 512) // 229888 (< 227 KB limit)

// GEMM config
#define BM 128
#define BN 128
#define BK 16
#define LDT 132   // padded smem row stride (floats)

// ---------------- device scratch (no allocations allowed) ----------------
__device__ __align__(16) float  g_xg[(size_t)T_STEPS * G_DIM];   // 256 MB: x @ W_ih^T + bias
__device__ __align__(16) __half g_whh[(size_t)G_DIM * H_DIM];    // 32 MB fp16 W_hh
__device__ __align__(16) float  g_h[2][H_DIM];                   // double-buffered hidden state
__device__ unsigned g_bar;                                       // global barrier counter

// ---------------- helpers ----------------
__device__ __forceinline__ float sigmoidf_(float x) {
    return 1.0f / (1.0f + __expf(-x));
}
__device__ __forceinline__ float tanh_accf(float x) {
    float xc = fminf(fmaxf(x, -15.0f), 15.0f);
    float e  = __expf(2.0f * xc);
    return (e - 1.0f) / (e + 1.0f);
}

// packed f32x2 FMA (Blackwell): 2 fp32 MACs per instruction
__device__ __forceinline__ unsigned long long pk2(float x, float y) {
    unsigned long long r;
    asm("mov.b64 %0, {%1, %2};" : "=l"(r) : "f"(x), "f"(y));
    return r;
}
__device__ __forceinline__ void fma2(unsigned long long& a, unsigned long long m, unsigned long long n) {
    asm("fma.rn.f32x2 %0, %1, %2, %0;" : "+l"(a) : "l"(m), "l"(n));
}
__device__ __forceinline__ void upk2(unsigned long long a, float& x, float& y) {
    asm("mov.b64 {%0, %1}, %2;" : "=f"(x), "=f"(y) : "l"(a));
}

// ---------------- kernel 0: per-launch state init ----------------
__global__ void init_state(const float* __restrict__ h0) {
    int i = blockIdx.x * blockDim.x + threadIdx.x;
    if (i < H_DIM) g_h[0][i] = h0[i];
    if (i == 0) g_bar = 0u;
}

// ---------------- kernel 1: W_hh fp32 -> fp16 ----------------
__global__ void convert_whh(const float* __restrict__ W) {
    const float2* src = (const float2*)W;
    __half2* dst = (__half2*)g_whh;
    size_t n2 = (size_t)G_DIM * H_DIM / 2;
    for (size_t u = (size_t)blockIdx.x * blockDim.x + threadIdx.x; u < n2;
         u += (size_t)gridDim.x * blockDim.x) {
        float2 v = src[u];
        dst[u] = __floats2half2_rn(v.x, v.y);
    }
}

// ---------------- kernel 2: x_gates GEMM (fp32, f32x2-packed FMA) ----------------
// C[t][n] = sum_k seq[t,k] * W_ih[n,k] + (b_ih[n] + b_hh[n])
__global__ void __launch_bounds__(256) gemm_xg(const float* __restrict__ A,   // seq [T, IN]
                                               const float* __restrict__ B,   // W_ih [4H, IN]
                                               const float* __restrict__ bih,
                                               const float* __restrict__ bhh) {
    __shared__ float As[BK * LDT];
    __shared__ float Bs[BK * LDT];
    const int tid = threadIdx.x;
    const int tx = tid & 15, ty = tid >> 4;
    const int bm = blockIdx.y, bn = blockIdx.x;

    unsigned long long acc[8][4];
#pragma unroll
    for (int i = 0; i < 8; i++)
#pragma unroll
        for (int jp = 0; jp < 4; jp++) acc[i][jp] = 0ULL;

    for (int kt = 0; kt < IN_DIM; kt += BK) {
#pragma unroll
        for (int r = 0; r < 2; r++) {
            int id = tid + r * 256;
            int mr = id >> 2, kc = id & 3;
            float4 av = *(const float4*)(A + (size_t)(bm * BM + mr) * IN_DIM + kt + kc * 4);
            As[(kc * 4 + 0) * LDT + mr] = av.x;
            As[(kc * 4 + 1) * LDT + mr] = av.y;
            As[(kc * 4 + 2) * LDT + mr] = av.z;
            As[(kc * 4 + 3) * LDT + mr] = av.w;
            float4 bv = *(const float4*)(B + (size_t)(bn * BN + mr) * IN_DIM + kt + kc * 4);
            Bs[(kc * 4 + 0) * LDT + mr] = bv.x;
            Bs[(kc * 4 + 1) * LDT + mr] = bv.y;
            Bs[(kc * 4 + 2) * LDT + mr] = bv.z;
            Bs[(kc * 4 + 3) * LDT + mr] = bv.w;
        }
        __syncthreads();
#pragma unroll
        for (int k = 0; k < BK; k++) {
            float4 a0 = *(const float4*)(As + k * LDT + ty * 8);
            float4 a1 = *(const float4*)(As + k * LDT + ty * 8 + 4);
            float4 b0 = *(const float4*)(Bs + k * LDT + tx * 8);
            float4 b1 = *(const float4*)(Bs + k * LDT + tx * 8 + 4);
            unsigned long long bb0 = pk2(b0.x, b0.y);
            unsigned long long bb1 = pk2(b0.z, b0.w);
            unsigned long long bb2 = pk2(b1.x, b1.y);
            unsigned long long bb3 = pk2(b1.z, b1.w);
            float aa[8] = {a0.x, a0.y, a0.z, a0.w, a1.x, a1.y, a1.z, a1.w};
#pragma unroll
            for (int i = 0; i < 8; i++) {
                unsigned long long a2 = pk2(aa[i], aa[i]);
                fma2(acc[i][0], a2, bb0);
                fma2(acc[i][1], a2, bb1);
                fma2(acc[i][2], a2, bb2);
                fma2(acc[i][3], a2, bb3);
            }
        }
        __syncthreads();
    }

    int n0 = bn * BN + tx * 8;
    float bias[8];
#pragma unroll
    for (int u = 0; u < 8; u++) bias[u] = bih[n0 + u] + bhh[n0 + u];
#pragma unroll
    for (int i = 0; i < 8; i++) {
        int m = bm * BM + ty * 8 + i;
        float r[8];
#pragma unroll
        for (int jp = 0; jp < 4; jp++) upk2(acc[i][jp], r[2 * jp], r[2 * jp + 1]);
#pragma unroll
        for (int u = 0; u < 8; u++) r[u] += bias[u];
        float4* out = (float4*)(g_xg + (size_t)m * G_DIM + n0);
        out[0] = make_float4(r[0], r[1], r[2], r[3]);
        out[1] = make_float4(r[4], r[5], r[6], r[7]);
    }
}

// ---------------- kernel 3: persistent LSTM recurrence ----------------
// CTA b owns hidden units [j0, j0+J): 124 CTAs x 14 + 24 CTAs x 13 = 2048.
// Local row lr (0..4J-1): gate = lr&3, j_local = lr>>2; global W_hh row = gate*2048 + j0 + j_local.
#define MAC8()                                          \
    {                                                   \
        const __half2* hp = (const __half2*)&wv;        \
        float2 f0 = __half22float2(hp[0]);              \
        float2 f1 = __half22float2(hp[1]);              \
        float2 f2 = __half22float2(hp[2]);              \
        float2 f3 = __half22float2(hp[3]);              \
        acc.x = fmaf(f0.x, hreg[i * 8 + 0], acc.x);     \
        acc.y = fmaf(f0.y, hreg[i * 8 + 1], acc.y);     \
        acc.z = fmaf(f1.x, hreg[i * 8 + 2], acc.z);     \
        acc.w = fmaf(f1.y, hreg[i * 8 + 3], acc.w);     \
        acc.x = fmaf(f2.x, hreg[i * 8 + 4], acc.x);     \
        acc.y = fmaf(f2.y, hreg[i * 8 + 5], acc.y);     \
        acc.z = fmaf(f3.x, hreg[i * 8 + 6], acc.z);     \
        acc.w = fmaf(f3.y, hreg[i * 8 + 7], acc.w);     \
    }

__global__ void __launch_bounds__(NTHR, 1) lstm_recur(const float* __restrict__ c0) {
    extern __shared__ unsigned char smem_raw[];
    __half* sw    = (__half*)smem_raw;                       // [SROWS_MAX][2048] fp16 weights
    float*  sh    = (float*)(smem_raw + SMEM_W_BYTES);       // [2048] staged h
    float*  sgate = sh + H_DIM;                              // [64] per-row dot results
    float*  sc    = sgate + 64;                              // [14] cell state

    const int tid = threadIdx.x;
    const int ln  = tid & 31;
    const int wid = tid >> 5;
    const int b   = blockIdx.x;

    int J, j0;
    if (b < 124) { J = 14; j0 = b * 14; }
    else         { J = 13; j0 = 124 * 14 + (b - 124) * 13; }
    const int R  = 4 * J;
    const int RS = (R < SROWS_MAX) ? R : SROWS_MAX;

    // Load this CTA's W_hh rows (fp16) into SMEM once.
    {
        const uint4* src = (const uint4*)g_whh;
        uint4* dst = (uint4*)sw;
        for (int idx = tid; idx < RS * 256; idx += NTHR) {
            int lr = idx >> 8, u = idx & 255;
            int grow = (lr & 3) * H_DIM + j0 + (lr >> 2);
            dst[(lr << 8) + u] = src[(size_t)grow * 256 + u];
        }
    }
    if (tid < J) sc[tid] = c0[j0 + tid];
    __syncthreads();

    int p = 0;
    for (int t = 0; t < T_STEPS; t++) {
        // Stage h_prev from L2 into SMEM (L2-only loads: other SMs wrote it).
        {
            const float4* src = (const float4*)g_h[p];
            float4* dst = (float4*)sh;
            for (int u = tid; u < H_DIM / 4; u += NTHR) dst[u] = __ldcg(src + u);
        }
        // Prefetch this step's x_gates contributions (hides DRAM latency behind matvec).
        float xgi = 0.f, xgf = 0.f, xgg = 0.f, xgo = 0.f;
        if (tid < J) {
            const float* xg = g_xg + (size_t)t * G_DIM + j0 + tid;
            xgi = __ldcg(xg);
            xgf = __ldcg(xg + H_DIM);
            xgg = __ldcg(xg + 2 * H_DIM);
            xgo = __ldcg(xg + 3 * H_DIM);
        }
        __syncthreads();

        // Each lane caches its 64 h values (k = ln*8 + i*256 + u) in registers.
        float hreg[64];
#pragma unroll
        for (int i = 0; i < 8; i++) {
            float4 a  = *(const float4*)(sh + ln * 8 + i * 256);
            float4 c2 = *(const float4*)(sh + ln * 8 + 4 + i * 256);
            hreg[i * 8 + 0] = a.x;  hreg[i * 8 + 1] = a.y;
            hreg[i * 8 + 2] = a.z;  hreg[i * 8 + 3] = a.w;
            hreg[i * 8 + 4] = c2.x; hreg[i * 8 + 5] = c2.y;
            hreg[i * 8 + 6] = c2.z; hreg[i * 8 + 7] = c2.w;
        }

        // Matvec: each warp handles rows lr = wid, wid+8, ...
        for (int lr = wid; lr < R; lr += 8) {
            float4 acc = make_float4(0.f, 0.f, 0.f, 0.f);
            if (lr < RS) {
                const uint4* wp = (const uint4*)(sw + (size_t)lr * H_DIM);
#pragma unroll
                for (int i = 0; i < 8; i++) {
                    uint4 wv = wp[ln + i * 32];
                    MAC8();
                }
            } else {  // overflow rows streamed from global (L1-resident, weights are constant)
                int grow = (lr & 3) * H_DIM + j0 + (lr >> 2);
                const uint4* wp = (const uint4*)(g_whh + (size_t)grow * H_DIM);
#pragma unroll
                for (int i = 0; i < 8; i++) {
                    uint4 wv = __ldg(wp + ln + i * 32);
                    MAC8();
                }
            }
            float s = (acc.x + acc.y) + (acc.z + acc.w);
#pragma unroll
            for (int sft = 16; sft >= 1; sft >>= 1) s += __shfl_xor_sync(0xffffffffu, s, sft);
            if (ln == 0) sgate[lr] = s;
        }
        __syncthreads();

        // Cell update for this CTA's J hidden units.
        if (tid < J) {
            float gi = sgate[tid * 4 + 0] + xgi;
            float gf = sgate[tid * 4 + 1] + xgf;
            float gg = sgate[tid * 4 + 2] + xgg;
            float go = sgate[tid * 4 + 3] + xgo;
            float i_ = sigmoidf_(gi);
            float f_ = sigmoidf_(gf);
            float g_ = tanh_accf(gg);
            float o_ = sigmoidf_(go);
            float c = f_ * sc[tid] + i_ * g_;
            sc[tid] = c;
            float h = o_ * tanh_accf(c);
            __stcg(&g_h[p ^ 1][j0 + tid], h);
            __threadfence();   // make h visible device-wide before barrier arrive
        }
        __syncthreads();

        // Lightweight grid barrier (monotonic counter, reset each launch by init_state).
        if (tid == 0) {
            atomicAdd(&g_bar, 1u);
            unsigned target = (unsigned)(t + 1) * (unsigned)NCTA;
            while (*(volatile unsigned*)&g_bar < target) { }
            __threadfence();
        }
        __syncthreads();
        p ^= 1;
    }
}

// ---------------- kernel 4: final linear on h_last (= g_h[0] since T even) ----------------
__global__ void __launch_bounds__(256) final_linear(const float* __restrict__ Wl,
                                                    const float* __restrict__ bl,
                                                    float* __restrict__ out) {
    int wid = threadIdx.x >> 5, ln = threadIdx.x & 31;
    int o = blockIdx.x * 8 + wid;
    const float4* w4 = (const float4*)(Wl + (size_t)o * H_DIM);
    const float4* h4 = (const float4*)g_h[0];
    float s = 0.f;
#pragma unroll
    for (int i = 0; i < 16; i++) {
        float4 w = __ldg(w4 + i * 32 + ln);
        float4 h = h4[i * 32 + ln];
        s += w.x * h.x + w.y * h.y + w.z * h.z + w.w * h.w;
    }
#pragma unroll
    for (int sft = 16; sft >= 1; sft >>= 1) s += __shfl_xor_sync(0xffffffffu, s, sft);
    if (ln == 0) out[o] = s + bl[o];
}

// ---------------- launcher ----------------
extern "C" void kernel_launch(void* const* d_in, const int* in_sizes, int n_in,
                              void* d_out, int out_size) {
    const float* seq  = (const float*)d_in[0];
    const float* Wih  = (const float*)d_in[1];
    const float* Whh  = (const float*)d_in[2];
    const float* bih  = (const float*)d_in[3];
    const float* bhh  = (const float*)d_in[4];
    const float* h0   = (const float*)d_in[5];
    const float* c0   = (const float*)d_in[6];
    const float* Wlin = (const float*)d_in[7];
    const float* blin = (const float*)d_in[8];
    float* out = (float*)d_out;

    cudaFuncSetAttribute(lstm_recur, cudaFuncAttributeMaxDynamicSharedMemorySize, SMEM_BYTES);

    init_state<<<8, 256>>>(h0);
    convert_whh<<<2048, 256>>>(Whh);
    gemm_xg<<<dim3(G_DIM / BN, T_STEPS / BM), 256>>>(seq, Wih, bih, bhh);
    lstm_recur<<<NCTA, NTHR, SMEM_BYTES>>>(c0);
    final_linear<<<OUT_DIM / 8, 256>>>(Wlin, blin, out);
}

// round 5
// speedup vs baseline: 1.1602x; 1.1602x over previous
#include <cuda_runtime.h>
#include <cuda_fp16.h>

// Problem dims
#define T_STEPS 8192
#define IN_DIM  512
#define H_DIM   2048
#define G_DIM   8192   // 4*H
#define OUT_DIM 512

// Persistent recurrence kernel config
#define NCTA      148
#define NTHR      512
#define SW_ROWS   55                    // W_hh rows resident in SMEM per CTA
#define SW_STRIDE 2056                  // halves per row (4112 B: +16B pad -> conflict-free ldmatrix)
#define SW_BYTES  (SW_ROWS * SW_STRIDE * 2)     // 226160
#define SH2_OFF   SW_BYTES                       // h fp16 staging: 2048*2 = 4096 B
#define SGATE_OFF (SH2_OFF + 4096)               // 64 floats
#define SC_OFF    (SGATE_OFF + 256)              // 16 floats
#define SMEM_BYTES (SC_OFF + 64 + 32)            // 230672 < 232448 max

// GEMM config
#define BM 128
#define BN 128
#define BK 16
#define LDT 132

// ---------------- device scratch ----------------
__device__ __align__(16) float  g_xg[(size_t)T_STEPS * G_DIM];   // x @ W_ih^T + bias
__device__ __align__(16) __half g_whh[(size_t)G_DIM * H_DIM];    // fp16 W_hh
__device__ __align__(16) __half g_hvec[2][H_DIM];                // double-buffered fp16 hidden
__device__ unsigned g_bar;

// ---------------- helpers ----------------
__device__ __forceinline__ float sigmoidf_(float x) { return 1.0f / (1.0f + __expf(-x)); }
__device__ __forceinline__ float tanh_accf(float x) {
    float xc = fminf(fmaxf(x, -15.0f), 15.0f);
    float e  = __expf(2.0f * xc);
    return (e - 1.0f) / (e + 1.0f);
}
__device__ __forceinline__ unsigned smem_u32(const void* p) {
    return (unsigned)__cvta_generic_to_shared(p);
}
__device__ __forceinline__ void ldsm4(unsigned& a0, unsigned& a1, unsigned& a2, unsigned& a3,
                                      unsigned addr) {
    asm volatile("ldmatrix.sync.aligned.m8n8.x4.shared.b16 {%0,%1,%2,%3},[%4];"
                 : "=r"(a0), "=r"(a1), "=r"(a2), "=r"(a3) : "r"(addr));
}
__device__ __forceinline__ unsigned lds32(unsigned addr) {
    unsigned v;
    asm volatile("ld.shared.b32 %0,[%1];" : "=r"(v) : "r"(addr));
    return v;
}
__device__ __forceinline__ void mma16816(float& c0, float& c1, float& c2, float& c3,
                                         unsigned a0, unsigned a1, unsigned a2, unsigned a3,
                                         unsigned b0, unsigned b1) {
    asm volatile("mma.sync.aligned.m16n8k16.row.col.f32.f16.f16.f32 "
                 "{%0,%1,%2,%3},{%4,%5,%6,%7},{%8,%9},{%0,%1,%2,%3};"
                 : "+f"(c0), "+f"(c1), "+f"(c2), "+f"(c3)
                 : "r"(a0), "r"(a1), "r"(a2), "r"(a3), "r"(b0), "r"(b1));
}

// packed f32x2 FMA helpers for the GEMM
__device__ __forceinline__ unsigned long long pk2(float x, float y) {
    unsigned long long r;
    asm("mov.b64 %0, {%1, %2};" : "=l"(r) : "f"(x), "f"(y));
    return r;
}
__device__ __forceinline__ void fma2(unsigned long long& a, unsigned long long m, unsigned long long n) {
    asm("fma.rn.f32x2 %0, %1, %2, %0;" : "+l"(a) : "l"(m), "l"(n));
}
__device__ __forceinline__ void upk2(unsigned long long a, float& x, float& y) {
    asm("mov.b64 {%0, %1}, %2;" : "=f"(x), "=f"(y) : "l"(a));
}

// ---------------- kernel 0: per-launch state init ----------------
__global__ void init_state(const float* __restrict__ h0) {
    int i = blockIdx.x * blockDim.x + threadIdx.x;
    if (i < H_DIM) g_hvec[0][i] = __float2half(h0[i]);
    if (i == 0) g_bar = 0u;
}

// ---------------- kernel 1: W_hh fp32 -> fp16 ----------------
__global__ void convert_whh(const float* __restrict__ W) {
    const float2* src = (const float2*)W;
    __half2* dst = (__half2*)g_whh;
    size_t n2 = (size_t)G_DIM * H_DIM / 2;
    for (size_t u = (size_t)blockIdx.x * blockDim.x + threadIdx.x; u < n2;
         u += (size_t)gridDim.x * blockDim.x) {
        float2 v = src[u];
        dst[u] = __floats2half2_rn(v.x, v.y);
    }
}

// ---------------- kernel 2: x_gates GEMM (fp32, f32x2 FMA) ----------------
__global__ void __launch_bounds__(256) gemm_xg(const float* __restrict__ A,
                                               const float* __restrict__ B,
                                               const float* __restrict__ bih,
                                               const float* __restrict__ bhh) {
    __shared__ float As[BK * LDT];
    __shared__ float Bs[BK * LDT];
    const int tid = threadIdx.x;
    const int tx = tid & 15, ty = tid >> 4;
    const int bm = blockIdx.y, bn = blockIdx.x;

    unsigned long long acc[8][4];
#pragma unroll
    for (int i = 0; i < 8; i++)
#pragma unroll
        for (int jp = 0; jp < 4; jp++) acc[i][jp] = 0ULL;

    for (int kt = 0; kt < IN_DIM; kt += BK) {
#pragma unroll
        for (int r = 0; r < 2; r++) {
            int id = tid + r * 256;
            int mr = id >> 2, kc = id & 3;
            float4 av = *(const float4*)(A + (size_t)(bm * BM + mr) * IN_DIM + kt + kc * 4);
            As[(kc * 4 + 0) * LDT + mr] = av.x;
            As[(kc * 4 + 1) * LDT + mr] = av.y;
            As[(kc * 4 + 2) * LDT + mr] = av.z;
            As[(kc * 4 + 3) * LDT + mr] = av.w;
            float4 bv = *(const float4*)(B + (size_t)(bn * BN + mr) * IN_DIM + kt + kc * 4);
            Bs[(kc * 4 + 0) * LDT + mr] = bv.x;
            Bs[(kc * 4 + 1) * LDT + mr] = bv.y;
            Bs[(kc * 4 + 2) * LDT + mr] = bv.z;
            Bs[(kc * 4 + 3) * LDT + mr] = bv.w;
        }
        __syncthreads();
#pragma unroll
        for (int k = 0; k < BK; k++) {
            float4 a0 = *(const float4*)(As + k * LDT + ty * 8);
            float4 a1 = *(const float4*)(As + k * LDT + ty * 8 + 4);
            float4 b0 = *(const float4*)(Bs + k * LDT + tx * 8);
            float4 b1 = *(const float4*)(Bs + k * LDT + tx * 8 + 4);
            unsigned long long bb0 = pk2(b0.x, b0.y);
            unsigned long long bb1 = pk2(b0.z, b0.w);
            unsigned long long bb2 = pk2(b1.x, b1.y);
            unsigned long long bb3 = pk2(b1.z, b1.w);
            float aa[8] = {a0.x, a0.y, a0.z, a0.w, a1.x, a1.y, a1.z, a1.w};
#pragma unroll
            for (int i = 0; i < 8; i++) {
                unsigned long long a2 = pk2(aa[i], aa[i]);
                fma2(acc[i][0], a2, bb0);
                fma2(acc[i][1], a2, bb1);
                fma2(acc[i][2], a2, bb2);
                fma2(acc[i][3], a2, bb3);
            }
        }
        __syncthreads();
    }

    int n0 = bn * BN + tx * 8;
    float bias[8];
#pragma unroll
    for (int u = 0; u < 8; u++) bias[u] = bih[n0 + u] + bhh[n0 + u];
#pragma unroll
    for (int i = 0; i < 8; i++) {
        int m = bm * BM + ty * 8 + i;
        float r[8];
#pragma unroll
        for (int jp = 0; jp < 4; jp++) upk2(acc[i][jp], r[2 * jp], r[2 * jp + 1]);
#pragma unroll
        for (int u = 0; u < 8; u++) r[u] += bias[u];
        float4* out = (float4*)(g_xg + (size_t)m * G_DIM + n0);
        out[0] = make_float4(r[0], r[1], r[2], r[3]);
        out[1] = make_float4(r[4], r[5], r[6], r[7]);
    }
}

// ---------------- kernel 3: persistent LSTM recurrence (tensor-core matvec) --
// CTA b owns units [j0, j0+J): 124 CTAs x 14 + 24 CTAs x 13.
// Local row lr: gate = lr&3, unit = lr>>2; W_hh row = gate*2048 + j0 + unit.
// Rows 0..RS-1 live in SMEM (RS = min(4J,55)); for J=14, row 55 handled by a
// scalar fp32-register path on warps 0-3.
__global__ void __launch_bounds__(NTHR, 1) lstm_recur(const float* __restrict__ c0,
                                                      const float* __restrict__ Whh32) {
    extern __shared__ unsigned char smem_raw[];
    __half* sw    = (__half*)smem_raw;                    // [55][2056] halves
    __half* sh2   = (__half*)(smem_raw + SH2_OFF);        // [2048] fp16 h
    float*  sgate = (float*)(smem_raw + SGATE_OFF);       // [64]
    float*  sc    = (float*)(smem_raw + SC_OFF);          // [16]

    const int tid  = threadIdx.x;
    const int lane = tid & 31;
    const int w    = tid >> 5;
    const int b    = blockIdx.x;

    int J, j0;
    if (b < 124) { J = 14; j0 = b * 14; }
    else         { J = 13; j0 = 124 * 14 + (b - 124) * 13; }
    const int R  = 4 * J;
    const int RS = (R < SW_ROWS) ? R : SW_ROWS;
    const bool do55 = (J == 14);

    // Load W_hh rows (fp16) into SMEM once (padded stride).
    // Each row = 2048 halves = 256 uint4.  (Round-4 bug: bound was RS*128,
    // leaving halves 1024..2047 of every row uninitialized -> NaN.)
    for (int idx = tid; idx < RS * 256; idx += NTHR) {
        int lr = idx >> 8, u = idx & 255;
        int grow = (lr & 3) * H_DIM + j0 + (lr >> 2);
        *(uint4*)(sw + lr * SW_STRIDE + u * 8) =
            *(const uint4*)(g_whh + (size_t)grow * H_DIM + u * 8);
    }
    // Row 55 fp32 weights in registers (warps 0-3, 16 per lane).
    float w55[16];
    if (do55 && w < 4) {
        const float* wr = Whh32 + (size_t)(3 * H_DIM + j0 + 13) * H_DIM + w * 512 + lane * 16;
#pragma unroll
        for (int u = 0; u < 16; u += 4) {
            float4 v = *(const float4*)(wr + u);
            w55[u] = v.x; w55[u + 1] = v.y; w55[u + 2] = v.z; w55[u + 3] = v.w;
        }
    }
    if (tid < J) sc[tid] = c0[j0 + tid];
    __syncthreads();

    // Per-warp MMA geometry: tile tw (16 rows), K-quarter kq (512 halves).
    const int tw = w & 3, kq = w >> 2;
    const int r_l   = tw * 16 + (lane & 15);
    const int r_eff = (r_l < RS) ? r_l : 0;           // clamp; results suppressed
    const unsigned a_base = smem_u32(sw) + (unsigned)r_eff * (SW_STRIDE * 2)
                          + ((lane >> 4) * 16) + (unsigned)kq * 1024;
    const unsigned b_base = smem_u32(sh2) + (unsigned)kq * 1024 + (lane & 3) * 4;
    const int  g_row   = tw * 16 + (lane >> 2);
    const bool ok_lo   = ((lane & 3) == 0) && (g_row < RS);
    const bool ok_hi   = ((lane & 3) == 0) && (g_row + 8 < RS);

    int p = 0;
    for (int t = 0; t < T_STEPS; t++) {
        if (tid < 64) sgate[tid] = 0.f;
        // x_gates prefetch (independent of h)
        float xgi = 0.f, xgf = 0.f, xgg = 0.f, xgo = 0.f;
        if (tid < J) {
            const float* xg = g_xg + (size_t)t * G_DIM + j0 + tid;
            xgi = __ldcg(xg);
            xgf = __ldcg(xg + H_DIM);
            xgg = __ldcg(xg + 2 * H_DIM);
            xgo = __ldcg(xg + 3 * H_DIM);
        }
        // Stage h (fp16) from L2 into SMEM: 512 threads x 8 B.
        {
            uint2 v = __ldcg((const uint2*)(g_hvec[p]) + tid);
            *(uint2*)(sh2 + tid * 4) = v;
        }
        __syncthreads();

        // Tensor-core matvec: 32 k16-steps per warp, 2 accumulator chains.
        {
            unsigned aa = a_base, bb = b_base;
            float cA0 = 0.f, cA1 = 0.f, cA2 = 0.f, cA3 = 0.f;
            float cB0 = 0.f, cB1 = 0.f, cB2 = 0.f, cB3 = 0.f;
#pragma unroll
            for (int j = 0; j < 32; j += 2) {
                unsigned a0, a1, a2, a3, b0, b1;
                ldsm4(a0, a1, a2, a3, aa);
                b0 = lds32(bb); b1 = lds32(bb + 16);
                mma16816(cA0, cA1, cA2, cA3, a0, a1, a2, a3, b0, b1);
                ldsm4(a0, a1, a2, a3, aa + 32);
                b0 = lds32(bb + 32); b1 = lds32(bb + 48);
                mma16816(cB0, cB1, cB2, cB3, a0, a1, a2, a3, b0, b1);
                aa += 64; bb += 64;
            }
            float d0 = cA0 + cB0;
            float d2 = cA2 + cB2;
            if (ok_lo) atomicAdd(&sgate[g_row], d0);
            if (ok_hi) atomicAdd(&sgate[g_row + 8], d2);
        }
        // Row 55 scalar path (J=14 CTAs; warps 0-3, 512 halves each).
        if (do55 && w < 4) {
            const __half2* hp = (const __half2*)(sh2 + w * 512 + lane * 16);
            float s = 0.f;
#pragma unroll
            for (int u = 0; u < 8; u++) {
                float2 f = __half22float2(hp[u]);
                s = fmaf(w55[2 * u], f.x, s);
                s = fmaf(w55[2 * u + 1], f.y, s);
            }
#pragma unroll
            for (int sft = 16; sft >= 1; sft >>= 1) s += __shfl_xor_sync(0xffffffffu, s, sft);
            if (lane == 0) atomicAdd(&sgate[55], s);
        }
        __syncthreads();

        // Cell update for this CTA's J units.
        if (tid < J) {
            float gi = sgate[tid * 4 + 0] + xgi;
            float gf = sgate[tid * 4 + 1] + xgf;
            float gg = sgate[tid * 4 + 2] + xgg;
            float go = sgate[tid * 4 + 3] + xgo;
            float i_ = sigmoidf_(gi);
            float f_ = sigmoidf_(gf);
            float g_ = tanh_accf(gg);
            float o_ = sigmoidf_(go);
            float c = f_ * sc[tid] + i_ * g_;
            sc[tid] = c;
            float h = o_ * tanh_accf(c);
            unsigned short hs = __half_as_ushort(__float2half(h));
            asm volatile("st.global.cg.u16 [%0], %1;"
                         :: "l"(&g_hvec[p ^ 1][j0 + tid]), "h"(hs) : "memory");
            __threadfence();
        }
        __syncthreads();

        // Grid barrier (monotonic counter, reset each launch).
        if (tid == 0) {
            atomicAdd(&g_bar, 1u);
            unsigned target = (unsigned)(t + 1) * (unsigned)NCTA;
            while (*(volatile unsigned*)&g_bar < target) { }
            __threadfence();
        }
        __syncthreads();
        p ^= 1;
    }
}

// ---------------- kernel 4: final linear on h_last (fp16) ----------------
__global__ void __launch_bounds__(256) final_linear(const float* __restrict__ Wl,
                                                    const float* __restrict__ bl,
                                                    float* __restrict__ out) {
    int wid = threadIdx.x >> 5, ln = threadIdx.x & 31;
    int o = blockIdx.x * 8 + wid;
    const float4* w4 = (const float4*)(Wl + (size_t)o * H_DIM);
    const uint2* h2 = (const uint2*)g_hvec[0];
    float s = 0.f;
#pragma unroll
    for (int i = 0; i < 16; i++) {
        float4 wv = __ldg(w4 + i * 32 + ln);
        uint2 hv = h2[i * 32 + ln];
        float2 h0 = __half22float2(*(__half2*)&hv.x);
        float2 h1 = __half22float2(*(__half2*)&hv.y);
        s += wv.x * h0.x + wv.y * h0.y + wv.z * h1.x + wv.w * h1.y;
    }
#pragma unroll
    for (int sft = 16; sft >= 1; sft >>= 1) s += __shfl_xor_sync(0xffffffffu, s, sft);
    if (ln == 0) out[o] = s + bl[o];
}

// ---------------- launcher ----------------
extern "C" void kernel_launch(void* const* d_in, const int* in_sizes, int n_in,
                              void* d_out, int out_size) {
    const float* seq  = (const float*)d_in[0];
    const float* Wih  = (const float*)d_in[1];
    const float* Whh  = (const float*)d_in[2];
    const float* bih  = (const float*)d_in[3];
    const float* bhh  = (const float*)d_in[4];
    const float* h0   = (const float*)d_in[5];
    const float* c0   = (const float*)d_in[6];
    const float* Wlin = (const float*)d_in[7];
    const float* blin = (const float*)d_in[8];
    float* out = (float*)d_out;

    cudaFuncSetAttribute(lstm_recur, cudaFuncAttributeMaxDynamicSharedMemorySize, SMEM_BYTES);

    init_state<<<8, 256>>>(h0);
    convert_whh<<<2048, 256>>>(Whh);
    gemm_xg<<<dim3(G_DIM / BN, T_STEPS / BM), 256>>>(seq, Wih, bih, bhh);
    lstm_recur<<<NCTA, NTHR, SMEM_BYTES>>>(c0, Whh);
    final_linear<<<OUT_DIM / 8, 256>>>(Wlin, blin, out);
}

// round 6
// speedup vs baseline: 1.5596x; 1.3443x over previous
#include <cuda_runtime.h>
#include <cuda_fp16.h>

// Problem dims
#define T_STEPS 8192
#define IN_DIM  512
#define H_DIM   2048
#define G_DIM   8192   // 4*H
#define OUT_DIM 512

// Persistent recurrence kernel config
#define NCTA      148
#define NTHR      512
#define R_MAX     56                       // max W_hh rows per CTA (4*14)
#define SW2_STRIDE_H 1032                  // halves per smem row (2064 B; 2064 % 128 == 16 -> conflict-free ldsm)
#define SW2_BYTES (R_MAX * 2064)           // 115584: smem keeps upper K-half of each quarter
#define SH2_OFF   SW2_BYTES                // h fp16 staging: 4096 B
#define SGATE_OFF (SH2_OFF + 4096)         // [4][64] float partials = 1024 B
#define SC_OFF    (SGATE_OFF + 1024)       // 16 floats
#define SMEM_BYTES (SC_OFF + 64 + 32)      // ~120.7 KB

// GEMM config
#define BM 128
#define BN 128
#define BK 16
#define LDT 132

// ---------------- device scratch ----------------
__device__ __align__(16) float  g_xg[(size_t)T_STEPS * G_DIM];   // x @ W_ih^T + bias
__device__ __align__(16) __half g_whh[(size_t)G_DIM * H_DIM];    // fp16 W_hh
__device__ __align__(16) __half g_hvec[2][H_DIM];                // double-buffered fp16 hidden
__device__ unsigned g_bar;

// ---------------- helpers ----------------
__device__ __forceinline__ float sigmoidf_(float x) { return 1.0f / (1.0f + __expf(-x)); }
__device__ __forceinline__ float tanh_accf(float x) {
    float xc = fminf(fmaxf(x, -15.0f), 15.0f);
    float e  = __expf(2.0f * xc);
    return (e - 1.0f) / (e + 1.0f);
}
__device__ __forceinline__ unsigned smem_u32(const void* p) {
    return (unsigned)__cvta_generic_to_shared(p);
}
__device__ __forceinline__ void ldsm4(unsigned& a0, unsigned& a1, unsigned& a2, unsigned& a3,
                                      unsigned addr) {
    asm volatile("ldmatrix.sync.aligned.m8n8.x4.shared.b16 {%0,%1,%2,%3},[%4];"
                 : "=r"(a0), "=r"(a1), "=r"(a2), "=r"(a3) : "r"(addr));
}
__device__ __forceinline__ void mma16816(float& c0, float& c1, float& c2, float& c3,
                                         unsigned a0, unsigned a1, unsigned a2, unsigned a3,
                                         unsigned b0, unsigned b1) {
    asm volatile("mma.sync.aligned.m16n8k16.row.col.f32.f16.f16.f32 "
                 "{%0,%1,%2,%3},{%4,%5,%6,%7},{%8,%9},{%0,%1,%2,%3};"
                 : "+f"(c0), "+f"(c1), "+f"(c2), "+f"(c3)
                 : "r"(a0), "r"(a1), "r"(a2), "r"(a3), "r"(b0), "r"(b1));
}

// packed f32x2 FMA helpers for the GEMM
__device__ __forceinline__ unsigned long long pk2(float x, float y) {
    unsigned long long r;
    asm("mov.b64 %0, {%1, %2};" : "=l"(r) : "f"(x), "f"(y));
    return r;
}
__device__ __forceinline__ void fma2(unsigned long long& a, unsigned long long m, unsigned long long n) {
    asm("fma.rn.f32x2 %0, %1, %2, %0;" : "+l"(a) : "l"(m), "l"(n));
}
__device__ __forceinline__ void upk2(unsigned long long a, float& x, float& y) {
    asm("mov.b64 {%0, %1}, %2;" : "=f"(x), "=f"(y) : "l"(a));
}

// ---------------- kernel 0: per-launch state init ----------------
__global__ void init_state(const float* __restrict__ h0) {
    int i = blockIdx.x * blockDim.x + threadIdx.x;
    if (i < H_DIM) g_hvec[0][i] = __float2half(h0[i]);
    if (i == 0) g_bar = 0u;
}

// ---------------- kernel 1: W_hh fp32 -> fp16 ----------------
__global__ void convert_whh(const float* __restrict__ W) {
    const float2* src = (const float2*)W;
    __half2* dst = (__half2*)g_whh;
    size_t n2 = (size_t)G_DIM * H_DIM / 2;
    for (size_t u = (size_t)blockIdx.x * blockDim.x + threadIdx.x; u < n2;
         u += (size_t)gridDim.x * blockDim.x) {
        float2 v = src[u];
        dst[u] = __floats2half2_rn(v.x, v.y);
    }
}

// ---------------- kernel 2: x_gates GEMM (fp32, f32x2 FMA) ----------------
__global__ void __launch_bounds__(256) gemm_xg(const float* __restrict__ A,
                                               const float* __restrict__ B,
                                               const float* __restrict__ bih,
                                               const float* __restrict__ bhh) {
    __shared__ float As[BK * LDT];
    __shared__ float Bs[BK * LDT];
    const int tid = threadIdx.x;
    const int tx = tid & 15, ty = tid >> 4;
    const int bm = blockIdx.y, bn = blockIdx.x;

    unsigned long long acc[8][4];
#pragma unroll
    for (int i = 0; i < 8; i++)
#pragma unroll
        for (int jp = 0; jp < 4; jp++) acc[i][jp] = 0ULL;

    for (int kt = 0; kt < IN_DIM; kt += BK) {
#pragma unroll
        for (int r = 0; r < 2; r++) {
            int id = tid + r * 256;
            int mr = id >> 2, kc = id & 3;
            float4 av = *(const float4*)(A + (size_t)(bm * BM + mr) * IN_DIM + kt + kc * 4);
            As[(kc * 4 + 0) * LDT + mr] = av.x;
            As[(kc * 4 + 1) * LDT + mr] = av.y;
            As[(kc * 4 + 2) * LDT + mr] = av.z;
            As[(kc * 4 + 3) * LDT + mr] = av.w;
            float4 bv = *(const float4*)(B + (size_t)(bn * BN + mr) * IN_DIM + kt + kc * 4);
            Bs[(kc * 4 + 0) * LDT + mr] = bv.x;
            Bs[(kc * 4 + 1) * LDT + mr] = bv.y;
            Bs[(kc * 4 + 2) * LDT + mr] = bv.z;
            Bs[(kc * 4 + 3) * LDT + mr] = bv.w;
        }
        __syncthreads();
#pragma unroll
        for (int k = 0; k < BK; k++) {
            float4 a0 = *(const float4*)(As + k * LDT + ty * 8);
            float4 a1 = *(const float4*)(As + k * LDT + ty * 8 + 4);
            float4 b0 = *(const float4*)(Bs + k * LDT + tx * 8);
            float4 b1 = *(const float4*)(Bs + k * LDT + tx * 8 + 4);
            unsigned long long bb0 = pk2(b0.x, b0.y);
            unsigned long long bb1 = pk2(b0.z, b0.w);
            unsigned long long bb2 = pk2(b1.x, b1.y);
            unsigned long long bb3 = pk2(b1.z, b1.w);
            float aa[8] = {a0.x, a0.y, a0.z, a0.w, a1.x, a1.y, a1.z, a1.w};
#pragma unroll
            for (int i = 0; i < 8; i++) {
                unsigned long long a2 = pk2(aa[i], aa[i]);
                fma2(acc[i][0], a2, bb0);
                fma2(acc[i][1], a2, bb1);
                fma2(acc[i][2], a2, bb2);
                fma2(acc[i][3], a2, bb3);
            }
        }
        __syncthreads();
    }

    int n0 = bn * BN + tx * 8;
    float bias[8];
#pragma unroll
    for (int u = 0; u < 8; u++) bias[u] = bih[n0 + u] + bhh[n0 + u];
#pragma unroll
    for (int i = 0; i < 8; i++) {
        int m = bm * BM + ty * 8 + i;
        float r[8];
#pragma unroll
        for (int jp = 0; jp < 4; jp++) upk2(acc[i][jp], r[2 * jp], r[2 * jp + 1]);
#pragma unroll
        for (int u = 0; u < 8; u++) r[u] += bias[u];
        float4* out = (float4*)(g_xg + (size_t)m * G_DIM + n0);
        out[0] = make_float4(r[0], r[1], r[2], r[3]);
        out[1] = make_float4(r[4], r[5], r[6], r[7]);
    }
}

// ---------------- kernel 3: persistent LSTM recurrence -----------------------
// CTA b owns units [j0, j0+J): 124 x 14 + 24 x 13. Local row lr: gate = lr&3,
// unit = lr>>2; global W_hh row = gate*2048 + j0 + unit.
// 16 warps = 4 row-tiles (16 rows) x 4 K-quarters (512 halves).
// Per warp: k16-steps 0..15 of its quarter held as A-fragments IN REGISTERS
// (loaded once); steps 16..31 read from SMEM via ldmatrix each step.
// B-fragments built by broadcast-ldmatrix from the staged h vector.
__global__ void __launch_bounds__(NTHR, 1) lstm_recur(const float* __restrict__ c0) {
    extern __shared__ unsigned char smem_raw[];
    __half* sw    = (__half*)smem_raw;                    // [56][1032] halves (upper K-half per quarter)
    __half* sh2   = (__half*)(smem_raw + SH2_OFF);        // [2048] fp16 h
    float*  sgate = (float*)(smem_raw + SGATE_OFF);       // [4][64] partials
    float*  sc    = (float*)(smem_raw + SC_OFF);          // [16]

    const int tid  = threadIdx.x;
    const int lane = tid & 31;
    const int w    = tid >> 5;
    const int b    = blockIdx.x;

    int J, j0;
    if (b < 124) { J = 14; j0 = b * 14; }
    else         { J = 13; j0 = 124 * 14 + (b - 124) * 13; }
    const int R = 4 * J;

    // Fill smem with the UPPER K-half of each quarter for all R rows:
    // row lr, quarter kq -> global halves [kq*512+256, kq*512+512).
    for (int idx = tid; idx < R * 128; idx += NTHR) {
        int lr = idx >> 7, rem = idx & 127;
        int kq = rem >> 5, u = rem & 31;
        int grow = (lr & 3) * H_DIM + j0 + (lr >> 2);
        *(uint4*)(sw + lr * SW2_STRIDE_H + kq * 256 + u * 8) =
            *(const uint4*)(g_whh + (size_t)grow * H_DIM + kq * 512 + 256 + u * 8);
    }
    if (tid < J) sc[tid] = c0[j0 + tid];

    const int tw = w & 3, kq = w >> 2;

    // A-fragments for steps 0..15 of this warp's quarter, loaded from global
    // into registers once. mma m16n8k16 A-frag: a0=A[l/4][2(l%4)+{0,1}],
    // a1=A[l/4+8][...], a2=a0 row k+8, a3=a1 row k+8.
    unsigned arg[64];
    {
        int r0l = 16 * tw + (lane >> 2);     if (r0l >= R) r0l = 0;
        int r1l = 16 * tw + (lane >> 2) + 8; if (r1l >= R) r1l = 0;
        int g0 = (r0l & 3) * H_DIM + j0 + (r0l >> 2);
        int g1 = (r1l & 3) * H_DIM + j0 + (r1l >> 2);
        const unsigned* p0 = (const unsigned*)(g_whh + (size_t)g0 * H_DIM + kq * 512 + (lane & 3) * 2);
        const unsigned* p1 = (const unsigned*)(g_whh + (size_t)g1 * H_DIM + kq * 512 + (lane & 3) * 2);
#pragma unroll
        for (int j = 0; j < 16; j++) {
            arg[4 * j + 0] = p0[j * 8];
            arg[4 * j + 1] = p1[j * 8];
            arg[4 * j + 2] = p0[j * 8 + 4];
            arg[4 * j + 3] = p1[j * 8 + 4];
        }
    }
    __syncthreads();

    // A-ldsm base (smem steps): lanes 0-15 -> rows, lanes 16-31 -> +16B (k+8)
    const int r_l   = 16 * tw + (lane & 15);
    const int r_eff = (r_l < R) ? r_l : 0;
    const unsigned abase = smem_u32(sw) + (unsigned)r_eff * 2064 + (unsigned)kq * 512
                         + ((lane >> 4) * 16);
    // B broadcast-ldsm base: groups of 8 lanes each point at one 16B k-window.
    const unsigned bbase = smem_u32(sh2) + (unsigned)kq * 1024 + ((lane >> 3) * 16);

    const int  g_row = 16 * tw + (lane >> 2);
    const bool ok_lo = ((lane & 3) == 0) && (g_row < R);
    const bool ok_hi = ((lane & 3) == 0) && (g_row + 8 < R);

    int p = 0;
    for (int t = 0; t < T_STEPS; t++) {
        // x_gates prefetch for this step (independent of h; overlaps the spin)
        float xgi = 0.f, xgf = 0.f, xgg = 0.f, xgo = 0.f;
        if (tid < J) {
            const float* xg = g_xg + (size_t)t * G_DIM + j0 + tid;
            xgi = __ldcg(xg);
            xgf = __ldcg(xg + H_DIM);
            xgg = __ldcg(xg + 2 * H_DIM);
            xgo = __ldcg(xg + 3 * H_DIM);
        }
        // Wait for all CTAs to have published h for step t.
        if (tid == 0) {
            unsigned target = (unsigned)t * (unsigned)NCTA;
            while (*(volatile unsigned*)&g_bar < target) { }
        }
        __syncthreads();
        // Stage h (fp16) from L2 into SMEM: 512 threads x 8 B.
        {
            uint2 v = __ldcg((const uint2*)(g_hvec[p]) + tid);
            *(uint2*)(sh2 + tid * 4) = v;
        }
        __syncthreads();

        // Tensor-core matvec.
        float cA0 = 0.f, cA1 = 0.f, cA2 = 0.f, cA3 = 0.f;
        float cB0 = 0.f, cB1 = 0.f, cB2 = 0.f, cB3 = 0.f;
        // Register-A steps 0..15 (pairs): one B-ldsm serves 2 steps.
#pragma unroll
        for (int pr = 0; pr < 8; pr++) {
            unsigned t0, t1, t2, t3;
            ldsm4(t0, t1, t2, t3, bbase + pr * 64);
            mma16816(cA0, cA1, cA2, cA3,
                     arg[8 * pr + 0], arg[8 * pr + 1], arg[8 * pr + 2], arg[8 * pr + 3], t0, t1);
            mma16816(cB0, cB1, cB2, cB3,
                     arg[8 * pr + 4], arg[8 * pr + 5], arg[8 * pr + 6], arg[8 * pr + 7], t2, t3);
        }
        // SMEM-A steps 16..31.
#pragma unroll
        for (int pr = 0; pr < 8; pr++) {
            unsigned a0, a1, a2, a3, a4, a5, a6, a7, t0, t1, t2, t3;
            ldsm4(a0, a1, a2, a3, abase + pr * 64);
            ldsm4(a4, a5, a6, a7, abase + pr * 64 + 32);
            ldsm4(t0, t1, t2, t3, bbase + 512 + pr * 64);
            mma16816(cA0, cA1, cA2, cA3, a0, a1, a2, a3, t0, t1);
            mma16816(cB0, cB1, cB2, cB3, a4, a5, a6, a7, t2, t3);
        }
        float d0 = cA0 + cB0;
        float d2 = cA2 + cB2;
        // Per-quarter partial sums (no atomics, no zeroing).
        if (ok_lo) sgate[kq * 64 + g_row] = d0;
        if (ok_hi) sgate[kq * 64 + g_row + 8] = d2;
        __syncthreads();

        // Cell update (warp 0 only: J <= 14 < 32).
        if (tid < J) {
            int lr = tid * 4;
            float gi = sgate[lr + 0] + sgate[64 + lr + 0] + sgate[128 + lr + 0] + sgate[192 + lr + 0] + xgi;
            float gf = sgate[lr + 1] + sgate[64 + lr + 1] + sgate[128 + lr + 1] + sgate[192 + lr + 1] + xgf;
            float gg = sgate[lr + 2] + sgate[64 + lr + 2] + sgate[128 + lr + 2] + sgate[192 + lr + 2] + xgg;
            float go = sgate[lr + 3] + sgate[64 + lr + 3] + sgate[128 + lr + 3] + sgate[192 + lr + 3] + xgo;
            float i_ = sigmoidf_(gi);
            float f_ = sigmoidf_(gf);
            float g_ = tanh_accf(gg);
            float o_ = sigmoidf_(go);
            float c = f_ * sc[tid] + i_ * g_;
            sc[tid] = c;
            float h = o_ * tanh_accf(c);
            unsigned short hs = __half_as_ushort(__float2half(h));
            asm volatile("st.global.cg.u16 [%0], %1;"
                         :: "l"(&g_hvec[p ^ 1][j0 + tid]), "h"(hs) : "memory");
        }
        // Publish: fence + arrive confined to warp 0.
        if (w == 0) {
            __threadfence();
            __syncwarp();
            if (lane == 0) atomicAdd(&g_bar, 1u);
        }
        p ^= 1;
    }
}

// ---------------- kernel 4: final linear on h_last (fp16) ----------------
__global__ void __launch_bounds__(256) final_linear(const float* __restrict__ Wl,
                                                    const float* __restrict__ bl,
                                                    float* __restrict__ out) {
    int wid = threadIdx.x >> 5, ln = threadIdx.x & 31;
    int o = blockIdx.x * 8 + wid;
    const float4* w4 = (const float4*)(Wl + (size_t)o * H_DIM);
    const uint2* h2 = (const uint2*)g_hvec[0];
    float s = 0.f;
#pragma unroll
    for (int i = 0; i < 16; i++) {
        float4 wv = __ldg(w4 + i * 32 + ln);
        uint2 hv = h2[i * 32 + ln];
        float2 h0 = __half22float2(*(__half2*)&hv.x);
        float2 h1 = __half22float2(*(__half2*)&hv.y);
        s += wv.x * h0.x + wv.y * h0.y + wv.z * h1.x + wv.w * h1.y;
    }
#pragma unroll
    for (int sft = 16; sft >= 1; sft >>= 1) s += __shfl_xor_sync(0xffffffffu, s, sft);
    if (ln == 0) out[o] = s + bl[o];
}

// ---------------- launcher ----------------
extern "C" void kernel_launch(void* const* d_in, const int* in_sizes, int n_in,
                              void* d_out, int out_size) {
    const float* seq  = (const float*)d_in[0];
    const float* Wih  = (const float*)d_in[1];
    const float* Whh  = (const float*)d_in[2];
    const float* bih  = (const float*)d_in[3];
    const float* bhh  = (const float*)d_in[4];
    const float* h0   = (const float*)d_in[5];
    const float* c0   = (const float*)d_in[6];
    const float* Wlin = (const float*)d_in[7];
    const float* blin = (const float*)d_in[8];
    float* out = (float*)d_out;

    cudaFuncSetAttribute(lstm_recur, cudaFuncAttributeMaxDynamicSharedMemorySize, SMEM_BYTES);

    init_state<<<8, 256>>>(h0);
    convert_whh<<<2048, 256>>>(Whh);
    gemm_xg<<<dim3(G_DIM / BN, T_STEPS / BM), 256>>>(seq, Wih, bih, bhh);
    lstm_recur<<<NCTA, NTHR, SMEM_BYTES>>>(c0);
    final_linear<<<OUT_DIM / 8, 256>>>(Wlin, blin, out);
}